// round 10
// baseline (speedup 1.0000x reference)
#include <cuda_runtime.h>

#define NN 100000
#define NE 640000
#define NF 128
#define NC 16

typedef unsigned long long u64;

// Scratch (allocation-free rule: __device__ globals)
__device__ float g_yl[NN * NC];   // x @ W_l^T
__device__ float g_yr[NN * NC];   // x @ W_r^T
__device__ float g_agg[NN * NC];  // segment-sum of yl over edges
__device__ float g_deg[NN];       // in-degree (float)

__device__ __forceinline__ u64 fma2(u64 a, u64 b, u64 c) {
    u64 d;
    asm("fma.rn.f32x2 %0, %1, %2, %3;" : "=l"(d) : "l"(a), "l"(b), "l"(c));
    return d;
}
__device__ __forceinline__ u64 bcast2(float x) {
    u64 d;
    asm("mov.b64 %0, {%1, %1};" : "=l"(d) : "f"(x));
    return d;
}
__device__ __forceinline__ u64 pack2(float lo, float hi) {
    u64 d;
    asm("mov.b64 %0, {%1, %2};" : "=l"(d) : "f"(lo), "f"(hi));
    return d;
}
__device__ __forceinline__ void unpack2(u64 d, float& lo, float& hi) {
    asm("mov.b64 {%0, %1}, %2;" : "=f"(lo), "=f"(hi) : "l"(d));
}

// ---------------------------------------------------------------------------
// K1: dual projection, 2 threads per node (channel-half split).
// half=0 thread computes the full yl row (channels 0..15 as 8 f32x2 accs),
// half=1 thread computes the full yr row. 200k threads -> grid 1563 @128thr,
// ~48-56 regs -> high occupancy (the R8 version was 196 CTAs / 106 regs /
// occ 17% and latency-bound at issue=27%).
// Weights are k-major in smem: sW2k[k][p] (rows of 16 u64 = 128B). For a
// given k the two halves read disjoint 64B chunks of the SAME 128B line ->
// conflict-free dual broadcast. Each LDS.128 yields 2 channel-pairs.
// Also zero-inits g_agg/g_deg (replaces k_zero; scatter is ordered after).
// ---------------------------------------------------------------------------
__global__ __launch_bounds__(128, 8) void k_proj(const float* __restrict__ x,
                                                 const float* __restrict__ Wl,
                                                 const float* __restrict__ Wr) {
    __shared__ __align__(16) u64 sW2k[NF * 16];  // 16 KB, [k][p]
    int tid = threadIdx.x;
    for (int j = tid; j < NF * 16; j += 128) {
        int k = j >> 4;
        int p = j & 15;
        const float* r0;
        const float* r1;
        if (p < 8) {
            r0 = Wl + (2 * p) * NF;
            r1 = Wl + (2 * p + 1) * NF;
        } else {
            r0 = Wr + (2 * (p - 8)) * NF;
            r1 = Wr + (2 * (p - 8) + 1) * NF;
        }
        sW2k[j] = pack2(r0[k], r1[k]);
    }
    __syncthreads();

    int gid = blockIdx.x * 128 + tid;
    if (gid >= 2 * NN) return;
    int node = gid >> 1;
    int half = gid & 1;

    // zero-init agg + deg (split between the two halves of each node)
    {
        float4* a = reinterpret_cast<float4*>(g_agg + (size_t)node * NC + half * 8);
        a[0] = make_float4(0.f, 0.f, 0.f, 0.f);
        a[1] = make_float4(0.f, 0.f, 0.f, 0.f);
        if (half == 0) g_deg[node] = 0.f;
    }

    u64 acc[8];
#pragma unroll
    for (int p = 0; p < 8; p++) acc[p] = 0ull;

    const float4* xr = reinterpret_cast<const float4*>(x + (size_t)node * NF);
    const u64* wbase = sW2k + half * 8;  // this half's 64B chunk of each row

#pragma unroll 4
    for (int k4 = 0; k4 < 32; k4++) {
        float4 xv = xr[k4];
#pragma unroll
        for (int j = 0; j < 4; j++) {
            int k = k4 * 4 + j;
            float xs = (j == 0) ? xv.x : (j == 1) ? xv.y : (j == 2) ? xv.z : xv.w;
            u64 xa = bcast2(xs);
            const ulonglong2* w = reinterpret_cast<const ulonglong2*>(wbase + (size_t)k * 16);
            ulonglong2 w01 = w[0];
            ulonglong2 w23 = w[1];
            ulonglong2 w45 = w[2];
            ulonglong2 w67 = w[3];
            acc[0] = fma2(xa, w01.x, acc[0]);
            acc[1] = fma2(xa, w01.y, acc[1]);
            acc[2] = fma2(xa, w23.x, acc[2]);
            acc[3] = fma2(xa, w23.y, acc[3]);
            acc[4] = fma2(xa, w45.x, acc[4]);
            acc[5] = fma2(xa, w45.y, acc[5]);
            acc[6] = fma2(xa, w67.x, acc[6]);
            acc[7] = fma2(xa, w67.y, acc[7]);
        }
    }

    float v[16];
#pragma unroll
    for (int p = 0; p < 8; p++) unpack2(acc[p], v[2 * p], v[2 * p + 1]);

    float* dst = (half == 0 ? g_yl : g_yr) + (size_t)node * NC;
    float4* d4 = reinterpret_cast<float4*>(dst);
#pragma unroll
    for (int q = 0; q < 4; q++)
        d4[q] = make_float4(v[q * 4 + 0], v[q * 4 + 1], v[q * 4 + 2], v[q * 4 + 3]);
}

// ---------------------------------------------------------------------------
// K2: edge scatter, 4 threads per edge (thread = edge x quarter-row).
// Each thread: 1 LDG.128 gather + 1 red.global.add.v4.f32; q==0 adds degree.
// ---------------------------------------------------------------------------
__global__ __launch_bounds__(256) void k_scatter(const int* __restrict__ ei) {
    int t = blockIdx.x * blockDim.x + threadIdx.x;
    if (t >= NE * 4) return;
    int e = t >> 2;
    int q = t & 3;
    unsigned src = (unsigned)ei[e];
    unsigned dst = (unsigned)ei[NE + e];
    if (src >= NN || dst >= NN) return;  // never taken with valid input

    float4 v = reinterpret_cast<const float4*>(g_yl)[(size_t)src * 4 + q];
    float* d = g_agg + (size_t)dst * NC + q * 4;
    asm volatile("red.global.add.v4.f32 [%0], {%1, %2, %3, %4};"
                 :: "l"(d), "f"(v.x), "f"(v.y), "f"(v.z), "f"(v.w)
                 : "memory");
    if (q == 0) atomicAdd(&g_deg[dst], 1.0f);
}

// ---------------------------------------------------------------------------
// K3: epilogue, 4 threads per node: out = relu(agg/max(deg,1) + b + yr)
// ---------------------------------------------------------------------------
__global__ __launch_bounds__(256) void k_finish(const float* __restrict__ b,
                                                float* __restrict__ out) {
    int t = blockIdx.x * blockDim.x + threadIdx.x;
    if (t >= NN * 4) return;
    int i = t >> 2;
    int q = t & 3;
    float inv = 1.0f / fmaxf(g_deg[i], 1.0f);

    float4 a = reinterpret_cast<const float4*>(g_agg)[(size_t)i * 4 + q];
    float4 y = reinterpret_cast<const float4*>(g_yr)[(size_t)i * 4 + q];
    float4 bb = reinterpret_cast<const float4*>(b)[q];
    float4 o;
    o.x = fmaxf(fmaf(a.x, inv, bb.x + y.x), 0.f);
    o.y = fmaxf(fmaf(a.y, inv, bb.y + y.y), 0.f);
    o.z = fmaxf(fmaf(a.z, inv, bb.z + y.z), 0.f);
    o.w = fmaxf(fmaf(a.w, inv, bb.w + y.w), 0.f);
    reinterpret_cast<float4*>(out)[(size_t)i * 4 + q] = o;
}

// ---------------------------------------------------------------------------
// Inputs (metadata order): x [N*F] f32, edge_index [2*E] i32,
//                          W_l [C*F] f32, b_l [C] f32, W_r [C*F] f32
// Output: [N*C] f32
// ---------------------------------------------------------------------------
extern "C" void kernel_launch(void* const* d_in, const int* in_sizes, int n_in,
                              void* d_out, int out_size) {
    const float* x = (const float*)d_in[0];
    const int* ei = (const int*)d_in[1];
    const float* Wl = (const float*)d_in[2];
    const float* bl = (const float*)d_in[3];
    const float* Wr = (const float*)d_in[4];
    float* out = (float*)d_out;

    k_proj<<<(2 * NN + 127) / 128, 128>>>(x, Wl, Wr);
    k_scatter<<<(NE * 4 + 255) / 256, 256>>>(ei);
    k_finish<<<(NN * 4 + 255) / 256, 256>>>(bl, out);
}